// round 1
// baseline (speedup 1.0000x reference)
#include <cuda_runtime.h>
#include <cuda_bf16.h>
#include <cstdint>
#include <cstddef>

// ---------------------------------------------------------------------------
// Problem constants
// ---------------------------------------------------------------------------
#define NIMG   2
#define CIN    64
#define HF     128
#define WF     128
#define NPIX   (HF*WF)        // 16384
#define HD     256
#define KCOL   (CIN*9)        // 576
#define HO     256
#define WO     256
#define NQ     (HO*WO)        // 65536
#define NROWS  (NIMG*4*NQ)    // 524288

// ---------------------------------------------------------------------------
// Scratch (device globals; allocation-free)
// ---------------------------------------------------------------------------
__device__ float g_col [(size_t)NIMG*NPIX*KCOL];   // im2col      ~75.5 MB
__device__ float g_coef[(size_t)NIMG*NPIX*HD];     // NHWC coef   ~33.5 MB
__device__ float g_freq[(size_t)NIMG*NPIX*HD];     // NHWC freq   ~33.5 MB
__device__ float g_x   [(size_t)NROWS*HD];         // activations ~512 MB
__device__ float g_h   [(size_t)NROWS*HD];         // activations ~512 MB
__device__ float g_area[(size_t)NROWS];            //             ~2 MB

// ---------------------------------------------------------------------------
// im2col: g_col[img][pix][ic*9 + ky*3 + kx], zero-padded 3x3
// ---------------------------------------------------------------------------
__global__ void k_im2col(const float* __restrict__ feat)
{
    size_t idx = (size_t)blockIdx.x * blockDim.x + threadIdx.x;
    const size_t total = (size_t)NIMG * NPIX * KCOL;
    if (idx >= total) return;
    int col = (int)(idx % KCOL);
    size_t pi = idx / KCOL;
    int pix = (int)(pi % NPIX);
    int img = (int)(pi / NPIX);
    int ic = col / 9;
    int k  = col % 9;
    int ky = k / 3, kx = k % 3;
    int y = pix / WF, x = pix % WF;
    int gy = y + ky - 1, gx = x + kx - 1;
    float v = 0.f;
    if ((unsigned)gy < (unsigned)HF && (unsigned)gx < (unsigned)WF)
        v = feat[(((size_t)img*CIN + ic)*HF + gy)*WF + gx];
    g_col[idx] = v;
}

// ---------------------------------------------------------------------------
// SGEMM (NT): C[m][n] = act( sum_k A[m][k]*B[n][k] + bias[n] )
// A: M x K row-major, B: N x K row-major, C: M x N row-major.
// BM=BN=64, BK=16, 256 threads, 4x4 per-thread microtile.
// M % 64 == 0, N % 64 == 0, K % 16 == 0 required.
// ---------------------------------------------------------------------------
__global__ __launch_bounds__(256)
void k_sgemm_nt(const float* __restrict__ A, const float* __restrict__ B,
                const float* __restrict__ bias, float* __restrict__ C,
                int M, int N, int K, int do_relu)
{
    __shared__ float As[16][64];
    __shared__ float Bs[16][64];

    const int tid = threadIdx.x;
    const int tx = tid & 15;          // 0..15 -> 4 output cols
    const int ty = tid >> 4;          // 0..15 -> 4 output rows
    const int m0 = blockIdx.y * 64;
    const int n0 = blockIdx.x * 64;

    const int lr = tid >> 2;          // 0..63 tile row
    const int lk = (tid & 3) * 4;     // 0,4,8,12

    const float* Ap = A + (size_t)(m0 + lr) * K + lk;
    const float* Bp = B + (size_t)(n0 + lr) * K + lk;

    float acc[4][4];
#pragma unroll
    for (int i = 0; i < 4; i++)
#pragma unroll
        for (int j = 0; j < 4; j++) acc[i][j] = 0.f;

    for (int k0 = 0; k0 < K; k0 += 16) {
        float4 a = *(const float4*)(Ap + k0);
        float4 b = *(const float4*)(Bp + k0);
        As[lk+0][lr] = a.x; As[lk+1][lr] = a.y; As[lk+2][lr] = a.z; As[lk+3][lr] = a.w;
        Bs[lk+0][lr] = b.x; Bs[lk+1][lr] = b.y; Bs[lk+2][lr] = b.z; Bs[lk+3][lr] = b.w;
        __syncthreads();
#pragma unroll
        for (int kk = 0; kk < 16; kk++) {
            float4 av = *(const float4*)&As[kk][ty*4];
            float4 bv = *(const float4*)&Bs[kk][tx*4];
            float aa[4] = {av.x, av.y, av.z, av.w};
            float bb[4] = {bv.x, bv.y, bv.z, bv.w};
#pragma unroll
            for (int i = 0; i < 4; i++)
#pragma unroll
                for (int j = 0; j < 4; j++)
                    acc[i][j] += aa[i] * bb[j];
        }
        __syncthreads();
    }

#pragma unroll
    for (int i = 0; i < 4; i++) {
        int m = m0 + ty*4 + i;
#pragma unroll
        for (int j = 0; j < 4; j++) {
            int n = n0 + tx*4 + j;
            float v = acc[i][j] + bias[n];
            if (do_relu) v = fmaxf(v, 0.f);
            C[(size_t)m * N + n] = v;
        }
    }
}

// ---------------------------------------------------------------------------
// Assemble: for each row r = ((img*4+s)*NQ + q) build
//   x[r][0..255] = coef(pix) * [cos(pi*qf), sin(pi*qf)],  area[r]
// 256 threads handle 2 rows (128 threads per row, thread t -> freq pair t).
// ---------------------------------------------------------------------------
__global__ __launch_bounds__(256)
void k_assemble(const float* __restrict__ coord, const float* __restrict__ cell,
                const float* __restrict__ phase_w)
{
    const int r = blockIdx.x * 2 + (threadIdx.x >> 7);
    const int t = threadIdx.x & 127;

    const int img = r >> 18;          // / (4*NQ), NQ=2^16
    const int s   = (r >> 16) & 3;
    const int q   = r & (NQ - 1);

    const float cy = coord[2*q + 0];
    const float cx = coord[2*q + 1];

    const float vx = (s & 2) ? 1.f : -1.f;
    const float vy = (s & 1) ? 1.f : -1.f;
    const float RX  = 1.f / 128.f;
    const float EPS = 1e-6f;
    const float LO  = -1.0f + 1e-6f;
    const float HI  =  1.0f - 1e-6f;

    float cys = fminf(fmaxf(cy + (vx*RX + EPS), LO), HI);
    float cxs = fminf(fmaxf(cx + (vy*RX + EPS), LO), HI);

    int iy = (int)rintf(((cys + 1.f)*128.f - 1.f)*0.5f);
    int ix = (int)rintf(((cxs + 1.f)*128.f - 1.f)*0.5f);
    iy = min(max(iy, 0), 127);
    ix = min(max(ix, 0), 127);

    const float qcy = -1.f + (1.f/128.f) + (2.f/128.f)*(float)iy;
    const float qcx = -1.f + (1.f/128.f) + (2.f/128.f)*(float)ix;
    const float rel0 = (cy - qcy) * 128.f;
    const float rel1 = (cx - qcx) * 128.f;

    if (t == 0)
        g_area[r] = fabsf(rel0 * rel1) + 1e-9f;

    const float rc0 = cell[2*q + 0] * 128.f;
    const float rc1 = cell[2*q + 1] * 128.f;
    const float ph  = rc0 * phase_w[2*t + 0] + rc1 * phase_w[2*t + 1];

    const int pix = iy * WF + ix;
    const float* fp = g_freq + ((size_t)img * NPIX + pix) * HD;
    const float* cp = g_coef + ((size_t)img * NPIX + pix) * HD;

    const float qf = fp[2*t] * rel0 + fp[2*t + 1] * rel1 + ph;
    float sv, cv;
    __sincosf(3.14159265358979f * qf, &sv, &cv);

    const size_t base = (size_t)r * HD;
    g_x[base + t]       = cp[t]       * cv;
    g_x[base + t + 128] = cp[t + 128] * sv;
}

// ---------------------------------------------------------------------------
// Finalize: layer4 (256 -> 3), area-weighted blend (order [3,2,1,0]),
// bilinear-border of inp, write NCHW output. One warp per (img, q).
// ---------------------------------------------------------------------------
__global__ __launch_bounds__(256)
void k_finalize(const float* __restrict__ inp, const float* __restrict__ coord,
                const float* __restrict__ w4, const float* __restrict__ b4,
                float* __restrict__ out)
{
    __shared__ float sw4[3 * HD];
    for (int i = threadIdx.x; i < 3 * HD; i += 256) sw4[i] = w4[i];
    __syncthreads();

    const int warp = threadIdx.x >> 5;
    const int lane = threadIdx.x & 31;
    const int gq = blockIdx.x * 8 + warp;          // 0 .. 131071
    const int img = gq >> 16;
    const int q   = gq & (NQ - 1);

    float pred[4][3];
    float area[4];

#pragma unroll
    for (int s = 0; s < 4; s++) {
        const size_t row = ((size_t)(img*4 + s) << 16) + q;
        const float* h = g_h + row * HD;
        float a0 = 0.f, a1 = 0.f, a2 = 0.f;
#pragma unroll
        for (int j = 0; j < 8; j++) {
            const int idx = lane + 32*j;
            const float hv = h[idx];
            a0 += hv * sw4[idx];
            a1 += hv * sw4[HD + idx];
            a2 += hv * sw4[2*HD + idx];
        }
#pragma unroll
        for (int off = 16; off; off >>= 1) {
            a0 += __shfl_xor_sync(0xffffffffu, a0, off);
            a1 += __shfl_xor_sync(0xffffffffu, a1, off);
            a2 += __shfl_xor_sync(0xffffffffu, a2, off);
        }
        pred[s][0] = a0 + b4[0];
        pred[s][1] = a1 + b4[1];
        pred[s][2] = a2 + b4[2];
        area[s] = g_area[row];
    }

    const float tot = area[0] + area[1] + area[2] + area[3];
    const float w0 = area[3] / tot;   // order = [3,2,1,0]
    const float w1 = area[2] / tot;
    const float w2 = area[1] / tot;
    const float w3 = area[0] / tot;

    float ret[3];
#pragma unroll
    for (int c = 0; c < 3; c++)
        ret[c] = pred[0][c]*w0 + pred[1][c]*w1 + pred[2][c]*w2 + pred[3][c]*w3;

    // bilinear (border clamp) on inp at coord
    const float cy = coord[2*q + 0];
    const float cx = coord[2*q + 1];
    float y = fminf(fmaxf(((cy + 1.f)*128.f - 1.f)*0.5f, 0.f), 127.f);
    float x = fminf(fmaxf(((cx + 1.f)*128.f - 1.f)*0.5f, 0.f), 127.f);
    float y0f = floorf(y), x0f = floorf(x);
    int y0 = (int)y0f, x0 = (int)x0f;
    float wy = y - y0f, wx = x - x0f;
    int y1 = min(y0 + 1, 127), x1 = min(x0 + 1, 127);

    if (lane < 3) {
        const float* ip = inp + ((size_t)img*3 + lane) * NPIX;
        float v00 = ip[y0*WF + x0];
        float v01 = ip[y0*WF + x1];
        float v10 = ip[y1*WF + x0];
        float v11 = ip[y1*WF + x1];
        float bv = v00*(1.f-wy)*(1.f-wx) + v01*(1.f-wy)*wx
                 + v10*wy*(1.f-wx)       + v11*wy*wx;
        out[(((size_t)img*3 + lane) << 16) + q] = ret[lane] + bv;
    }
}

// ---------------------------------------------------------------------------
// Launch
// ---------------------------------------------------------------------------
extern "C" void kernel_launch(void* const* d_in, const int* in_sizes, int n_in,
                              void* d_out, int out_size)
{
    const float* feat    = (const float*)d_in[0];
    const float* inp     = (const float*)d_in[1];
    const float* coord   = (const float*)d_in[2];
    const float* cell    = (const float*)d_in[3];
    const float* coef_w  = (const float*)d_in[4];
    const float* coef_b  = (const float*)d_in[5];
    const float* freq_w  = (const float*)d_in[6];
    const float* freq_b  = (const float*)d_in[7];
    const float* phase_w = (const float*)d_in[8];
    const float* w1 = (const float*)d_in[9],  *b1 = (const float*)d_in[10];
    const float* w2 = (const float*)d_in[11], *b2 = (const float*)d_in[12];
    const float* w3 = (const float*)d_in[13], *b3 = (const float*)d_in[14];
    const float* w4 = (const float*)d_in[15], *b4 = (const float*)d_in[16];
    float* out = (float*)d_out;

    void *p_col, *p_coef, *p_freq, *p_x, *p_h;
    cudaGetSymbolAddress(&p_col,  g_col);
    cudaGetSymbolAddress(&p_coef, g_coef);
    cudaGetSymbolAddress(&p_freq, g_freq);
    cudaGetSymbolAddress(&p_x,    g_x);
    cudaGetSymbolAddress(&p_h,    g_h);
    float* col_f  = (float*)p_col;
    float* coef_f = (float*)p_coef;
    float* freq_f = (float*)p_freq;
    float* x_f    = (float*)p_x;
    float* h_f    = (float*)p_h;

    // 1) im2col (both images)
    {
        const size_t total = (size_t)NIMG * NPIX * KCOL;
        k_im2col<<<(unsigned)((total + 255) / 256), 256>>>(feat);
    }

    // 2) conv-as-GEMM: coef & freq, NHWC output
    for (int img = 0; img < NIMG; img++) {
        const float* A = col_f + (size_t)img * NPIX * KCOL;
        k_sgemm_nt<<<dim3(HD/64, NPIX/64), 256>>>(
            A, coef_w, coef_b, coef_f + (size_t)img * NPIX * HD,
            NPIX, HD, KCOL, 0);
        k_sgemm_nt<<<dim3(HD/64, NPIX/64), 256>>>(
            A, freq_w, freq_b, freq_f + (size_t)img * NPIX * HD,
            NPIX, HD, KCOL, 0);
    }

    // 3) per-query assemble -> g_x rows
    k_assemble<<<NROWS/2, 256>>>(coord, cell, phase_w);

    // 4) MLP layers 1..3 (ping-pong g_x <-> g_h)
    k_sgemm_nt<<<dim3(HD/64, NROWS/64), 256>>>(x_f, w1, b1, h_f, NROWS, HD, HD, 1);
    k_sgemm_nt<<<dim3(HD/64, NROWS/64), 256>>>(h_f, w2, b2, x_f, NROWS, HD, HD, 1);
    k_sgemm_nt<<<dim3(HD/64, NROWS/64), 256>>>(x_f, w3, b3, h_f, NROWS, HD, HD, 1);

    // 5) layer4 + area blend + bilinear + write out
    k_finalize<<<(NIMG*NQ)/8, 256>>>(inp, coord, w4, b4, out);
}

// round 4
// speedup vs baseline: 1.3367x; 1.3367x over previous
#include <cuda_runtime.h>
#include <cuda_bf16.h>
#include <cstdint>
#include <cstddef>

// ---------------------------------------------------------------------------
// Problem constants
// ---------------------------------------------------------------------------
#define NIMG   2
#define CIN    64
#define HF     128
#define WF     128
#define NPIX   (HF*WF)        // 16384
#define HD     256
#define KCOL   (CIN*9)        // 576
#define HO     256
#define WO     256
#define NQ     (HO*WO)        // 65536
#define NROWS  (NIMG*4*NQ)    // 524288

// ---------------------------------------------------------------------------
// Scratch (device globals; allocation-free)
// ---------------------------------------------------------------------------
__device__ float g_col [(size_t)NIMG*NPIX*KCOL];   // im2col      ~75.5 MB
__device__ float g_coef[(size_t)NIMG*NPIX*HD];     // NHWC coef   ~33.5 MB
__device__ float g_freq[(size_t)NIMG*NPIX*HD];     // NHWC freq   ~33.5 MB
__device__ float g_x   [(size_t)NROWS*HD];         // activations ~512 MB
__device__ float g_h   [(size_t)NROWS*HD];         // activations ~512 MB
__device__ float g_area[(size_t)NROWS];            //             ~2 MB

// ---------------------------------------------------------------------------
// im2col: g_col[img][pix][ic*9 + ky*3 + kx], zero-padded 3x3
// ---------------------------------------------------------------------------
__global__ void k_im2col(const float* __restrict__ feat)
{
    size_t idx = (size_t)blockIdx.x * blockDim.x + threadIdx.x;
    const size_t total = (size_t)NIMG * NPIX * KCOL;
    if (idx >= total) return;
    int col = (int)(idx % KCOL);
    size_t pi = idx / KCOL;
    int pix = (int)(pi % NPIX);
    int img = (int)(pi / NPIX);
    int ic = col / 9;
    int k  = col % 9;
    int ky = k / 3, kx = k % 3;
    int y = pix / WF, x = pix % WF;
    int gy = y + ky - 1, gx = x + kx - 1;
    float v = 0.f;
    if ((unsigned)gy < (unsigned)HF && (unsigned)gx < (unsigned)WF)
        v = feat[(((size_t)img*CIN + ic)*HF + gy)*WF + gx];
    g_col[idx] = v;
}

// ---------------------------------------------------------------------------
// SGEMM (NT): C[m][n] = act( sum_k A[m][k]*B[n][k] + bias[n] )
// A: M x K row-major, B: N x K row-major, C: M x N row-major.
// BM=BN=128, BK=8, 256 threads, 8x8 per-thread microtile, double-buffered.
// Requires M % 128 == 0, N % 128 == 0, K % 8 == 0.
// ---------------------------------------------------------------------------
__global__ __launch_bounds__(256)
void k_sgemm128(const float* __restrict__ A, const float* __restrict__ B,
                const float* __restrict__ bias, float* __restrict__ C,
                int M, int N, int K, int do_relu)
{
    __shared__ float As[2][8][132];   // [buf][k][m] padded
    __shared__ float Bs[2][8][132];   // [buf][k][n] padded

    const int tid = threadIdx.x;
    const int tx = tid & 15;          // 0..15 -> 8 output cols each
    const int ty = tid >> 4;          // 0..15 -> 8 output rows each
    const int m0 = blockIdx.y * 128;
    const int n0 = blockIdx.x * 128;

    // global-load mapping: thread -> (row lr, k-offset lc), one float4 each
    const int lr = tid >> 1;          // 0..127
    const int lc = (tid & 1) * 4;     // 0 or 4

    const float* Ap = A + (size_t)(m0 + lr) * K + lc;
    const float* Bp = B + (size_t)(n0 + lr) * K + lc;

    float acc[8][8];
#pragma unroll
    for (int i = 0; i < 8; i++)
#pragma unroll
        for (int j = 0; j < 8; j++) acc[i][j] = 0.f;

    // prologue: load first k-slab into buffer 0
    {
        float4 a = *(const float4*)(Ap);
        float4 b = *(const float4*)(Bp);
        As[0][lc+0][lr] = a.x; As[0][lc+1][lr] = a.y;
        As[0][lc+2][lr] = a.z; As[0][lc+3][lr] = a.w;
        Bs[0][lc+0][lr] = b.x; Bs[0][lc+1][lr] = b.y;
        Bs[0][lc+2][lr] = b.z; Bs[0][lc+3][lr] = b.w;
    }
    __syncthreads();

    int buf = 0;
    for (int k0 = 0; k0 < K; k0 += 8) {
        const bool more = (k0 + 8) < K;
        float4 an, bn;
        if (more) {
            an = *(const float4*)(Ap + k0 + 8);
            bn = *(const float4*)(Bp + k0 + 8);
        }

#pragma unroll
        for (int kk = 0; kk < 8; kk++) {
            float av[8], bv[8];
            *(float4*)&av[0] = *(const float4*)&As[buf][kk][ty*8];
            *(float4*)&av[4] = *(const float4*)&As[buf][kk][ty*8 + 4];
            *(float4*)&bv[0] = *(const float4*)&Bs[buf][kk][tx*8];
            *(float4*)&bv[4] = *(const float4*)&Bs[buf][kk][tx*8 + 4];
#pragma unroll
            for (int i = 0; i < 8; i++)
#pragma unroll
                for (int j = 0; j < 8; j++)
                    acc[i][j] += av[i] * bv[j];
        }

        if (more) {
            buf ^= 1;
            As[buf][lc+0][lr] = an.x; As[buf][lc+1][lr] = an.y;
            As[buf][lc+2][lr] = an.z; As[buf][lc+3][lr] = an.w;
            Bs[buf][lc+0][lr] = bn.x; Bs[buf][lc+1][lr] = bn.y;
            Bs[buf][lc+2][lr] = bn.z; Bs[buf][lc+3][lr] = bn.w;
            __syncthreads();
        }
    }

    // epilogue: bias (+ReLU), vectorized stores
    float4 bia0 = *(const float4*)(bias + n0 + tx*8);
    float4 bia1 = *(const float4*)(bias + n0 + tx*8 + 4);
    const float bb[8] = {bia0.x, bia0.y, bia0.z, bia0.w,
                         bia1.x, bia1.y, bia1.z, bia1.w};
#pragma unroll
    for (int i = 0; i < 8; i++) {
        const int m = m0 + ty*8 + i;
        float v[8];
#pragma unroll
        for (int j = 0; j < 8; j++) {
            float t = acc[i][j] + bb[j];
            v[j] = do_relu ? fmaxf(t, 0.f) : t;
        }
        float* cp = C + (size_t)m * N + n0 + tx*8;
        *(float4*)(cp)     = make_float4(v[0], v[1], v[2], v[3]);
        *(float4*)(cp + 4) = make_float4(v[4], v[5], v[6], v[7]);
    }
}

// ---------------------------------------------------------------------------
// Assemble: for each row r = ((img*4+s)*NQ + q) build
//   x[r][0..255] = coef(pix) * [cos(pi*qf), sin(pi*qf)],  area[r]
// 256 threads handle 2 rows (128 threads per row, thread t -> freq pair t).
// ---------------------------------------------------------------------------
__global__ __launch_bounds__(256)
void k_assemble(const float* __restrict__ coord, const float* __restrict__ cell,
                const float* __restrict__ phase_w)
{
    const int r = blockIdx.x * 2 + (threadIdx.x >> 7);
    const int t = threadIdx.x & 127;

    const int img = r >> 18;          // / (4*NQ), NQ=2^16
    const int s   = (r >> 16) & 3;
    const int q   = r & (NQ - 1);

    const float cy = coord[2*q + 0];
    const float cx = coord[2*q + 1];

    const float vx = (s & 2) ? 1.f : -1.f;
    const float vy = (s & 1) ? 1.f : -1.f;
    const float RX  = 1.f / 128.f;
    const float EPS = 1e-6f;
    const float LO  = -1.0f + 1e-6f;
    const float HI  =  1.0f - 1e-6f;

    float cys = fminf(fmaxf(cy + (vx*RX + EPS), LO), HI);
    float cxs = fminf(fmaxf(cx + (vy*RX + EPS), LO), HI);

    int iy = (int)rintf(((cys + 1.f)*128.f - 1.f)*0.5f);
    int ix = (int)rintf(((cxs + 1.f)*128.f - 1.f)*0.5f);
    iy = min(max(iy, 0), 127);
    ix = min(max(ix, 0), 127);

    const float qcy = -1.f + (1.f/128.f) + (2.f/128.f)*(float)iy;
    const float qcx = -1.f + (1.f/128.f) + (2.f/128.f)*(float)ix;
    const float rel0 = (cy - qcy) * 128.f;
    const float rel1 = (cx - qcx) * 128.f;

    if (t == 0)
        g_area[r] = fabsf(rel0 * rel1) + 1e-9f;

    const float rc0 = cell[2*q + 0] * 128.f;
    const float rc1 = cell[2*q + 1] * 128.f;
    const float ph  = rc0 * phase_w[2*t + 0] + rc1 * phase_w[2*t + 1];

    const int pix = iy * WF + ix;
    const float* fp = g_freq + ((size_t)img * NPIX + pix) * HD;
    const float* cp = g_coef + ((size_t)img * NPIX + pix) * HD;

    const float qf = fp[2*t] * rel0 + fp[2*t + 1] * rel1 + ph;
    float sv, cv;
    __sincosf(3.14159265358979f * qf, &sv, &cv);

    const size_t base = (size_t)r * HD;
    g_x[base + t]       = cp[t]       * cv;
    g_x[base + t + 128] = cp[t + 128] * sv;
}

// ---------------------------------------------------------------------------
// Finalize: layer4 (256 -> 3), area-weighted blend (order [3,2,1,0]),
// bilinear-border of inp, write NCHW output. One warp per (img, q).
// ---------------------------------------------------------------------------
__global__ __launch_bounds__(256)
void k_finalize(const float* __restrict__ inp, const float* __restrict__ coord,
                const float* __restrict__ w4, const float* __restrict__ b4,
                float* __restrict__ out)
{
    __shared__ float sw4[3 * HD];
    for (int i = threadIdx.x; i < 3 * HD; i += 256) sw4[i] = w4[i];
    __syncthreads();

    const int warp = threadIdx.x >> 5;
    const int lane = threadIdx.x & 31;
    const int gq = blockIdx.x * 8 + warp;          // 0 .. 131071
    const int img = gq >> 16;
    const int q   = gq & (NQ - 1);

    float pred[4][3];
    float area[4];

#pragma unroll
    for (int s = 0; s < 4; s++) {
        const size_t row = ((size_t)(img*4 + s) << 16) + q;
        const float* h = g_h + row * HD;
        float a0 = 0.f, a1 = 0.f, a2 = 0.f;
#pragma unroll
        for (int j = 0; j < 8; j++) {
            const int idx = lane + 32*j;
            const float hv = h[idx];
            a0 += hv * sw4[idx];
            a1 += hv * sw4[HD + idx];
            a2 += hv * sw4[2*HD + idx];
        }
#pragma unroll
        for (int off = 16; off; off >>= 1) {
            a0 += __shfl_xor_sync(0xffffffffu, a0, off);
            a1 += __shfl_xor_sync(0xffffffffu, a1, off);
            a2 += __shfl_xor_sync(0xffffffffu, a2, off);
        }
        pred[s][0] = a0 + b4[0];
        pred[s][1] = a1 + b4[1];
        pred[s][2] = a2 + b4[2];
        area[s] = g_area[row];
    }

    const float tot = area[0] + area[1] + area[2] + area[3];
    const float w0 = area[3] / tot;   // order = [3,2,1,0]
    const float w1 = area[2] / tot;
    const float w2 = area[1] / tot;
    const float w3 = area[0] / tot;

    float ret[3];
#pragma unroll
    for (int c = 0; c < 3; c++)
        ret[c] = pred[0][c]*w0 + pred[1][c]*w1 + pred[2][c]*w2 + pred[3][c]*w3;

    // bilinear (border clamp) on inp at coord
    const float cy = coord[2*q + 0];
    const float cx = coord[2*q + 1];
    float y = fminf(fmaxf(((cy + 1.f)*128.f - 1.f)*0.5f, 0.f), 127.f);
    float x = fminf(fmaxf(((cx + 1.f)*128.f - 1.f)*0.5f, 0.f), 127.f);
    float y0f = floorf(y), x0f = floorf(x);
    int y0 = (int)y0f, x0 = (int)x0f;
    float wy = y - y0f, wx = x - x0f;
    int y1 = min(y0 + 1, 127), x1 = min(x0 + 1, 127);

    if (lane < 3) {
        const float* ip = inp + ((size_t)img*3 + lane) * NPIX;
        float v00 = ip[y0*WF + x0];
        float v01 = ip[y0*WF + x1];
        float v10 = ip[y1*WF + x0];
        float v11 = ip[y1*WF + x1];
        float bv = v00*(1.f-wy)*(1.f-wx) + v01*(1.f-wy)*wx
                 + v10*wy*(1.f-wx)       + v11*wy*wx;
        out[(((size_t)img*3 + lane) << 16) + q] = ret[lane] + bv;
    }
}

// ---------------------------------------------------------------------------
// Launch
// ---------------------------------------------------------------------------
extern "C" void kernel_launch(void* const* d_in, const int* in_sizes, int n_in,
                              void* d_out, int out_size)
{
    const float* feat    = (const float*)d_in[0];
    const float* inp     = (const float*)d_in[1];
    const float* coord   = (const float*)d_in[2];
    const float* cell    = (const float*)d_in[3];
    const float* coef_w  = (const float*)d_in[4];
    const float* coef_b  = (const float*)d_in[5];
    const float* freq_w  = (const float*)d_in[6];
    const float* freq_b  = (const float*)d_in[7];
    const float* phase_w = (const float*)d_in[8];
    const float* w1 = (const float*)d_in[9],  *b1 = (const float*)d_in[10];
    const float* w2 = (const float*)d_in[11], *b2 = (const float*)d_in[12];
    const float* w3 = (const float*)d_in[13], *b3 = (const float*)d_in[14];
    const float* w4 = (const float*)d_in[15], *b4 = (const float*)d_in[16];
    float* out = (float*)d_out;

    void *p_col, *p_coef, *p_freq, *p_x, *p_h;
    cudaGetSymbolAddress(&p_col,  g_col);
    cudaGetSymbolAddress(&p_coef, g_coef);
    cudaGetSymbolAddress(&p_freq, g_freq);
    cudaGetSymbolAddress(&p_x,    g_x);
    cudaGetSymbolAddress(&p_h,    g_h);
    float* col_f  = (float*)p_col;
    float* coef_f = (float*)p_coef;
    float* freq_f = (float*)p_freq;
    float* x_f    = (float*)p_x;
    float* h_f    = (float*)p_h;

    // 1) im2col (both images)
    {
        const size_t total = (size_t)NIMG * NPIX * KCOL;
        k_im2col<<<(unsigned)((total + 255) / 256), 256>>>(feat);
    }

    // 2) conv-as-GEMM: coef & freq, NHWC output
    for (int img = 0; img < NIMG; img++) {
        const float* A = col_f + (size_t)img * NPIX * KCOL;
        k_sgemm128<<<dim3(HD/128, NPIX/128), 256>>>(
            A, coef_w, coef_b, coef_f + (size_t)img * NPIX * HD,
            NPIX, HD, KCOL, 0);
        k_sgemm128<<<dim3(HD/128, NPIX/128), 256>>>(
            A, freq_w, freq_b, freq_f + (size_t)img * NPIX * HD,
            NPIX, HD, KCOL, 0);
    }

    // 3) per-query assemble -> g_x rows
    k_assemble<<<NROWS/2, 256>>>(coord, cell, phase_w);

    // 4) MLP layers 1..3 (ping-pong g_x <-> g_h)
    k_sgemm128<<<dim3(HD/128, NROWS/128), 256>>>(x_f, w1, b1, h_f, NROWS, HD, HD, 1);
    k_sgemm128<<<dim3(HD/128, NROWS/128), 256>>>(h_f, w2, b2, x_f, NROWS, HD, HD, 1);
    k_sgemm128<<<dim3(HD/128, NROWS/128), 256>>>(x_f, w3, b3, h_f, NROWS, HD, HD, 1);

    // 5) layer4 + area blend + bilinear + write out
    k_finalize<<<(NIMG*NQ)/8, 256>>>(inp, coord, w4, b4, out);
}

// round 5
// speedup vs baseline: 2.6897x; 2.0122x over previous
#include <cuda_runtime.h>
#include <cuda_bf16.h>
#include <cstdint>
#include <cstddef>

// ---------------------------------------------------------------------------
// Problem constants
// ---------------------------------------------------------------------------
#define NIMG   2
#define CIN    64
#define HF     128
#define WF     128
#define NPIX   (HF*WF)        // 16384
#define HD     256
#define KCOL   (CIN*9)        // 576
#define HO     256
#define WO     256
#define NQ     (HO*WO)        // 65536
#define NROWS  (NIMG*4*NQ)    // 524288

// ---------------------------------------------------------------------------
// Scratch (device globals; allocation-free)
// ---------------------------------------------------------------------------
__device__ float g_col [(size_t)NIMG*NPIX*KCOL];   // im2col      ~75.5 MB
__device__ float g_coef[(size_t)NIMG*NPIX*HD];     // NHWC coef   ~33.5 MB
__device__ float g_freq[(size_t)NIMG*NPIX*HD];     // NHWC freq   ~33.5 MB
__device__ float g_x   [(size_t)NROWS*HD];         // activations ~512 MB
__device__ float g_h   [(size_t)NROWS*HD];         // activations ~512 MB
__device__ float g_area[(size_t)NROWS];            //             ~2 MB

__device__ __forceinline__ uint32_t f2tf32(float f)
{
    uint32_t r;
    asm("cvt.rna.tf32.f32 %0, %1;" : "=r"(r) : "f"(f));
    return r;
}

// ---------------------------------------------------------------------------
// im2col: g_col[img][pix][ic*9 + ky*3 + kx], zero-padded 3x3
// ---------------------------------------------------------------------------
__global__ void k_im2col(const float* __restrict__ feat)
{
    size_t idx = (size_t)blockIdx.x * blockDim.x + threadIdx.x;
    const size_t total = (size_t)NIMG * NPIX * KCOL;
    if (idx >= total) return;
    int col = (int)(idx % KCOL);
    size_t pi = idx / KCOL;
    int pix = (int)(pi % NPIX);
    int img = (int)(pi / NPIX);
    int ic = col / 9;
    int k  = col % 9;
    int ky = k / 3, kx = k % 3;
    int y = pix / WF, x = pix % WF;
    int gy = y + ky - 1, gx = x + kx - 1;
    float v = 0.f;
    if ((unsigned)gy < (unsigned)HF && (unsigned)gx < (unsigned)WF)
        v = feat[(((size_t)img*CIN + ic)*HF + gy)*WF + gx];
    g_col[idx] = v;
}

// ---------------------------------------------------------------------------
// TF32 tensor-core GEMM (NT): C[m][n] = act(sum_k A[m][k]*B[n][k] + bias[n])
// A: M x K row-major fp32, B: N x K row-major fp32 (weights), C row-major.
// BM=BN=128, BK=16, 256 threads (8 warps, 2x4), warp tile 64x32,
// mma.sync m16n8k8 tf32, double-buffered smem, pad-20 conflict-free rows.
// Requires M%128==0, N%128==0, K%16==0.
// ---------------------------------------------------------------------------
#define SMPAD 20            // floats per smem row (16 data + 4 pad); 20*dr+dc unique mod 32
__global__ __launch_bounds__(256, 2)
void k_mma_tf32(const float* __restrict__ A, const float* __restrict__ B,
                const float* __restrict__ bias, float* __restrict__ C,
                int M, int N, int K, int do_relu)
{
    __shared__ uint32_t As[2][128*SMPAD];
    __shared__ uint32_t Bs[2][128*SMPAD];

    const int tid  = threadIdx.x;
    const int warp = tid >> 5;
    const int lane = tid & 31;
    const int wm   = warp & 1;        // 0..1 -> 64-row slice
    const int wn   = warp >> 1;       // 0..3 -> 32-col slice
    const int m0 = blockIdx.y * 128;
    const int n0 = blockIdx.x * 128;

    // global->smem mapping: each thread loads 8 consecutive floats of one row
    const int grow = tid >> 1;            // 0..127
    const int gcol = (tid & 1) * 8;       // 0 or 8
    const float* Ap = A + (size_t)(m0 + grow) * K + gcol;
    const float* Bp = B + (size_t)(n0 + grow) * K + gcol;
    const int sbase = grow * SMPAD + gcol;

    float acc[4][4][4];
#pragma unroll
    for (int mt = 0; mt < 4; mt++)
#pragma unroll
        for (int nt = 0; nt < 4; nt++)
#pragma unroll
            for (int r = 0; r < 4; r++) acc[mt][nt][r] = 0.f;

    // fragment base offsets (add mt*16*SMPAD / nt*8*SMPAD / ks*8 later)
    const int abase = (wm*64 + (lane>>2)) * SMPAD + (lane & 3);
    const int bbase = (wn*32 + (lane>>2)) * SMPAD + (lane & 3);

    // prologue: slab 0 -> buffer 0
    {
        float4 a0 = *(const float4*)(Ap);
        float4 a1 = *(const float4*)(Ap + 4);
        float4 b0 = *(const float4*)(Bp);
        float4 b1 = *(const float4*)(Bp + 4);
        As[0][sbase+0]=f2tf32(a0.x); As[0][sbase+1]=f2tf32(a0.y);
        As[0][sbase+2]=f2tf32(a0.z); As[0][sbase+3]=f2tf32(a0.w);
        As[0][sbase+4]=f2tf32(a1.x); As[0][sbase+5]=f2tf32(a1.y);
        As[0][sbase+6]=f2tf32(a1.z); As[0][sbase+7]=f2tf32(a1.w);
        Bs[0][sbase+0]=f2tf32(b0.x); Bs[0][sbase+1]=f2tf32(b0.y);
        Bs[0][sbase+2]=f2tf32(b0.z); Bs[0][sbase+3]=f2tf32(b0.w);
        Bs[0][sbase+4]=f2tf32(b1.x); Bs[0][sbase+5]=f2tf32(b1.y);
        Bs[0][sbase+6]=f2tf32(b1.z); Bs[0][sbase+7]=f2tf32(b1.w);
    }
    __syncthreads();

    const int nslab = K >> 4;
    int buf = 0;
    for (int s = 0; s < nslab; s++) {
        const bool more = (s + 1) < nslab;
        float4 pa0, pa1, pb0, pb1;
        if (more) {
            const int ko = (s + 1) << 4;
            pa0 = *(const float4*)(Ap + ko);
            pa1 = *(const float4*)(Ap + ko + 4);
            pb0 = *(const float4*)(Bp + ko);
            pb1 = *(const float4*)(Bp + ko + 4);
        }

        const uint32_t* as = As[buf];
        const uint32_t* bs = Bs[buf];
#pragma unroll
        for (int ks = 0; ks < 2; ks++) {
            uint32_t af[4][4], bf[4][2];
#pragma unroll
            for (int mt = 0; mt < 4; mt++) {
                const int o = abase + mt*(16*SMPAD) + ks*8;
                af[mt][0] = as[o];
                af[mt][1] = as[o + 8*SMPAD];
                af[mt][2] = as[o + 4];
                af[mt][3] = as[o + 8*SMPAD + 4];
            }
#pragma unroll
            for (int nt = 0; nt < 4; nt++) {
                const int o = bbase + nt*(8*SMPAD) + ks*8;
                bf[nt][0] = bs[o];
                bf[nt][1] = bs[o + 4];
            }
#pragma unroll
            for (int mt = 0; mt < 4; mt++)
#pragma unroll
                for (int nt = 0; nt < 4; nt++) {
                    asm volatile(
                        "mma.sync.aligned.m16n8k8.row.col.f32.tf32.tf32.f32 "
                        "{%0,%1,%2,%3}, {%4,%5,%6,%7}, {%8,%9}, {%0,%1,%2,%3};\n"
                        : "+f"(acc[mt][nt][0]), "+f"(acc[mt][nt][1]),
                          "+f"(acc[mt][nt][2]), "+f"(acc[mt][nt][3])
                        : "r"(af[mt][0]), "r"(af[mt][1]),
                          "r"(af[mt][2]), "r"(af[mt][3]),
                          "r"(bf[nt][0]), "r"(bf[nt][1]));
                }
        }

        if (more) {
            const int nb = buf ^ 1;
            As[nb][sbase+0]=f2tf32(pa0.x); As[nb][sbase+1]=f2tf32(pa0.y);
            As[nb][sbase+2]=f2tf32(pa0.z); As[nb][sbase+3]=f2tf32(pa0.w);
            As[nb][sbase+4]=f2tf32(pa1.x); As[nb][sbase+5]=f2tf32(pa1.y);
            As[nb][sbase+6]=f2tf32(pa1.z); As[nb][sbase+7]=f2tf32(pa1.w);
            Bs[nb][sbase+0]=f2tf32(pb0.x); Bs[nb][sbase+1]=f2tf32(pb0.y);
            Bs[nb][sbase+2]=f2tf32(pb0.z); Bs[nb][sbase+3]=f2tf32(pb0.w);
            Bs[nb][sbase+4]=f2tf32(pb1.x); Bs[nb][sbase+5]=f2tf32(pb1.y);
            Bs[nb][sbase+6]=f2tf32(pb1.z); Bs[nb][sbase+7]=f2tf32(pb1.w);
            __syncthreads();
            buf = nb;
        }
    }

    // epilogue: C fragment (r, 2q) (r, 2q+1) (r+8, ...) per (mt, nt)
#pragma unroll
    for (int mt = 0; mt < 4; mt++) {
        const int row = m0 + wm*64 + mt*16 + (lane >> 2);
#pragma unroll
        for (int nt = 0; nt < 4; nt++) {
            const int col = n0 + wn*32 + nt*8 + 2*(lane & 3);
            const float bz0 = bias[col];
            const float bz1 = bias[col + 1];
            float v0 = acc[mt][nt][0] + bz0;
            float v1 = acc[mt][nt][1] + bz1;
            float v2 = acc[mt][nt][2] + bz0;
            float v3 = acc[mt][nt][3] + bz1;
            if (do_relu) {
                v0 = fmaxf(v0, 0.f); v1 = fmaxf(v1, 0.f);
                v2 = fmaxf(v2, 0.f); v3 = fmaxf(v3, 0.f);
            }
            *(float2*)(C + (size_t)row * N + col)       = make_float2(v0, v1);
            *(float2*)(C + (size_t)(row + 8) * N + col) = make_float2(v2, v3);
        }
    }
}

// ---------------------------------------------------------------------------
// Assemble: for each row r = ((img*4+s)*NQ + q) build
//   x[r][0..255] = coef(pix) * [cos(pi*qf), sin(pi*qf)],  area[r]
// ---------------------------------------------------------------------------
__global__ __launch_bounds__(256)
void k_assemble(const float* __restrict__ coord, const float* __restrict__ cell,
                const float* __restrict__ phase_w)
{
    const int r = blockIdx.x * 2 + (threadIdx.x >> 7);
    const int t = threadIdx.x & 127;

    const int img = r >> 18;          // / (4*NQ), NQ=2^16
    const int s   = (r >> 16) & 3;
    const int q   = r & (NQ - 1);

    const float cy = coord[2*q + 0];
    const float cx = coord[2*q + 1];

    const float vx = (s & 2) ? 1.f : -1.f;
    const float vy = (s & 1) ? 1.f : -1.f;
    const float RX  = 1.f / 128.f;
    const float EPS = 1e-6f;
    const float LO  = -1.0f + 1e-6f;
    const float HI  =  1.0f - 1e-6f;

    float cys = fminf(fmaxf(cy + (vx*RX + EPS), LO), HI);
    float cxs = fminf(fmaxf(cx + (vy*RX + EPS), LO), HI);

    int iy = (int)rintf(((cys + 1.f)*128.f - 1.f)*0.5f);
    int ix = (int)rintf(((cxs + 1.f)*128.f - 1.f)*0.5f);
    iy = min(max(iy, 0), 127);
    ix = min(max(ix, 0), 127);

    const float qcy = -1.f + (1.f/128.f) + (2.f/128.f)*(float)iy;
    const float qcx = -1.f + (1.f/128.f) + (2.f/128.f)*(float)ix;
    const float rel0 = (cy - qcy) * 128.f;
    const float rel1 = (cx - qcx) * 128.f;

    if (t == 0)
        g_area[r] = fabsf(rel0 * rel1) + 1e-9f;

    const float rc0 = cell[2*q + 0] * 128.f;
    const float rc1 = cell[2*q + 1] * 128.f;
    const float ph  = rc0 * phase_w[2*t + 0] + rc1 * phase_w[2*t + 1];

    const int pix = iy * WF + ix;
    const float* fp = g_freq + ((size_t)img * NPIX + pix) * HD;
    const float* cp = g_coef + ((size_t)img * NPIX + pix) * HD;

    const float qf = fp[2*t] * rel0 + fp[2*t + 1] * rel1 + ph;
    float sv, cv;
    __sincosf(3.14159265358979f * qf, &sv, &cv);

    const size_t base = (size_t)r * HD;
    g_x[base + t]       = cp[t]       * cv;
    g_x[base + t + 128] = cp[t + 128] * sv;
}

// ---------------------------------------------------------------------------
// Finalize: layer4 (256 -> 3), area-weighted blend (order [3,2,1,0]),
// bilinear-border of inp, write NCHW output. One warp per (img, q).
// ---------------------------------------------------------------------------
__global__ __launch_bounds__(256)
void k_finalize(const float* __restrict__ inp, const float* __restrict__ coord,
                const float* __restrict__ w4, const float* __restrict__ b4,
                float* __restrict__ out)
{
    __shared__ float sw4[3 * HD];
    for (int i = threadIdx.x; i < 3 * HD; i += 256) sw4[i] = w4[i];
    __syncthreads();

    const int warp = threadIdx.x >> 5;
    const int lane = threadIdx.x & 31;
    const int gq = blockIdx.x * 8 + warp;          // 0 .. 131071
    const int img = gq >> 16;
    const int q   = gq & (NQ - 1);

    float pred[4][3];
    float area[4];

#pragma unroll
    for (int s = 0; s < 4; s++) {
        const size_t row = ((size_t)(img*4 + s) << 16) + q;
        const float* h = g_h + row * HD;
        float a0 = 0.f, a1 = 0.f, a2 = 0.f;
#pragma unroll
        for (int j = 0; j < 8; j++) {
            const int idx = lane + 32*j;
            const float hv = h[idx];
            a0 += hv * sw4[idx];
            a1 += hv * sw4[HD + idx];
            a2 += hv * sw4[2*HD + idx];
        }
#pragma unroll
        for (int off = 16; off; off >>= 1) {
            a0 += __shfl_xor_sync(0xffffffffu, a0, off);
            a1 += __shfl_xor_sync(0xffffffffu, a1, off);
            a2 += __shfl_xor_sync(0xffffffffu, a2, off);
        }
        pred[s][0] = a0 + b4[0];
        pred[s][1] = a1 + b4[1];
        pred[s][2] = a2 + b4[2];
        area[s] = g_area[row];
    }

    const float tot = area[0] + area[1] + area[2] + area[3];
    const float w0 = area[3] / tot;   // order = [3,2,1,0]
    const float w1 = area[2] / tot;
    const float w2 = area[1] / tot;
    const float w3 = area[0] / tot;

    float ret[3];
#pragma unroll
    for (int c = 0; c < 3; c++)
        ret[c] = pred[0][c]*w0 + pred[1][c]*w1 + pred[2][c]*w2 + pred[3][c]*w3;

    // bilinear (border clamp) on inp at coord
    const float cy = coord[2*q + 0];
    const float cx = coord[2*q + 1];
    float y = fminf(fmaxf(((cy + 1.f)*128.f - 1.f)*0.5f, 0.f), 127.f);
    float x = fminf(fmaxf(((cx + 1.f)*128.f - 1.f)*0.5f, 0.f), 127.f);
    float y0f = floorf(y), x0f = floorf(x);
    int y0 = (int)y0f, x0 = (int)x0f;
    float wy = y - y0f, wx = x - x0f;
    int y1 = min(y0 + 1, 127), x1 = min(x0 + 1, 127);

    if (lane < 3) {
        const float* ip = inp + ((size_t)img*3 + lane) * NPIX;
        float v00 = ip[y0*WF + x0];
        float v01 = ip[y0*WF + x1];
        float v10 = ip[y1*WF + x0];
        float v11 = ip[y1*WF + x1];
        float bv = v00*(1.f-wy)*(1.f-wx) + v01*(1.f-wy)*wx
                 + v10*wy*(1.f-wx)       + v11*wy*wx;
        out[(((size_t)img*3 + lane) << 16) + q] = ret[lane] + bv;
    }
}

// ---------------------------------------------------------------------------
// Launch
// ---------------------------------------------------------------------------
extern "C" void kernel_launch(void* const* d_in, const int* in_sizes, int n_in,
                              void* d_out, int out_size)
{
    const float* feat    = (const float*)d_in[0];
    const float* inp     = (const float*)d_in[1];
    const float* coord   = (const float*)d_in[2];
    const float* cell    = (const float*)d_in[3];
    const float* coef_w  = (const float*)d_in[4];
    const float* coef_b  = (const float*)d_in[5];
    const float* freq_w  = (const float*)d_in[6];
    const float* freq_b  = (const float*)d_in[7];
    const float* phase_w = (const float*)d_in[8];
    const float* w1 = (const float*)d_in[9],  *b1 = (const float*)d_in[10];
    const float* w2 = (const float*)d_in[11], *b2 = (const float*)d_in[12];
    const float* w3 = (const float*)d_in[13], *b3 = (const float*)d_in[14];
    const float* w4 = (const float*)d_in[15], *b4 = (const float*)d_in[16];
    float* out = (float*)d_out;

    void *p_col, *p_coef, *p_freq, *p_x, *p_h;
    cudaGetSymbolAddress(&p_col,  g_col);
    cudaGetSymbolAddress(&p_coef, g_coef);
    cudaGetSymbolAddress(&p_freq, g_freq);
    cudaGetSymbolAddress(&p_x,    g_x);
    cudaGetSymbolAddress(&p_h,    g_h);
    float* col_f  = (float*)p_col;
    float* coef_f = (float*)p_coef;
    float* freq_f = (float*)p_freq;
    float* x_f    = (float*)p_x;
    float* h_f    = (float*)p_h;

    // 1) im2col (both images)
    {
        const size_t total = (size_t)NIMG * NPIX * KCOL;
        k_im2col<<<(unsigned)((total + 255) / 256), 256>>>(feat);
    }

    // 2) conv-as-GEMM: coef & freq, NHWC output (tf32 tensor cores)
    for (int img = 0; img < NIMG; img++) {
        const float* A = col_f + (size_t)img * NPIX * KCOL;
        k_mma_tf32<<<dim3(HD/128, NPIX/128), 256>>>(
            A, coef_w, coef_b, coef_f + (size_t)img * NPIX * HD,
            NPIX, HD, KCOL, 0);
        k_mma_tf32<<<dim3(HD/128, NPIX/128), 256>>>(
            A, freq_w, freq_b, freq_f + (size_t)img * NPIX * HD,
            NPIX, HD, KCOL, 0);
    }

    // 3) per-query assemble -> g_x rows
    k_assemble<<<NROWS/2, 256>>>(coord, cell, phase_w);

    // 4) MLP layers 1..3 (ping-pong g_x <-> g_h, tf32 tensor cores)
    k_mma_tf32<<<dim3(HD/128, NROWS/128), 256>>>(x_f, w1, b1, h_f, NROWS, HD, HD, 1);
    k_mma_tf32<<<dim3(HD/128, NROWS/128), 256>>>(h_f, w2, b2, x_f, NROWS, HD, HD, 1);
    k_mma_tf32<<<dim3(HD/128, NROWS/128), 256>>>(x_f, w3, b3, h_f, NROWS, HD, HD, 1);

    // 5) layer4 + area blend + bilinear + write out
    k_finalize<<<(NIMG*NQ)/8, 256>>>(inp, coord, w4, b4, out);
}

// round 6
// speedup vs baseline: 2.8075x; 1.0438x over previous
#include <cuda_runtime.h>
#include <cuda_bf16.h>
#include <cstdint>
#include <cstddef>

// ---------------------------------------------------------------------------
// Problem constants
// ---------------------------------------------------------------------------
#define NIMG   2
#define CIN    64
#define HF     128
#define WF     128
#define NPIX   (HF*WF)        // 16384
#define HD     256
#define KCOL   (CIN*9)        // 576
#define HO     256
#define WO     256
#define NQ     (HO*WO)        // 65536
#define NROWS  (NIMG*4*NQ)    // 524288

// ---------------------------------------------------------------------------
// Scratch (device globals; allocation-free)
// ---------------------------------------------------------------------------
__device__ float g_col [(size_t)NIMG*NPIX*KCOL];   // im2col (tf32-rounded)
__device__ float g_coef[(size_t)NIMG*NPIX*HD];     // NHWC coef (fp32)
__device__ float g_freq[(size_t)NIMG*NPIX*HD];     // NHWC freq (fp32)
__device__ float g_x   [(size_t)NROWS*HD];         // activations
__device__ float g_h   [(size_t)NROWS*HD];         // activations
__device__ float g_area[(size_t)NROWS];
__device__ float g_wr  [3*HD*HD + 2*HD*KCOL];      // tf32-rounded weights

#define WR_W1    0
#define WR_W2    (HD*HD)
#define WR_W3    (2*HD*HD)
#define WR_COEFW (3*HD*HD)
#define WR_FREQW (3*HD*HD + HD*KCOL)

__device__ __forceinline__ uint32_t f2tf32(float f)
{
    uint32_t r;
    asm("cvt.rna.tf32.f32 %0, %1;" : "=r"(r) : "f"(f));
    return r;
}
__device__ __forceinline__ float roundtf(float f)
{
    return __uint_as_float(f2tf32(f));
}

// ---------------------------------------------------------------------------
// weight pre-round: dst[i] = tf32(src[i])
// ---------------------------------------------------------------------------
__global__ void k_round(const float* __restrict__ src, float* __restrict__ dst, int n)
{
    int i = blockIdx.x * blockDim.x + threadIdx.x;
    if (i < n) dst[i] = roundtf(src[i]);
}

// ---------------------------------------------------------------------------
// im2col: g_col[img][pix][ic*9 + ky*3 + kx], zero-padded 3x3, tf32-rounded
// ---------------------------------------------------------------------------
__global__ void k_im2col(const float* __restrict__ feat)
{
    size_t idx = (size_t)blockIdx.x * blockDim.x + threadIdx.x;
    const size_t total = (size_t)NIMG * NPIX * KCOL;
    if (idx >= total) return;
    int col = (int)(idx % KCOL);
    size_t pi = idx / KCOL;
    int pix = (int)(pi % NPIX);
    int img = (int)(pi / NPIX);
    int ic = col / 9;
    int k  = col % 9;
    int ky = k / 3, kx = k % 3;
    int y = pix / WF, x = pix % WF;
    int gy = y + ky - 1, gx = x + kx - 1;
    float v = 0.f;
    if ((unsigned)gy < (unsigned)HF && (unsigned)gx < (unsigned)WF)
        v = feat[(((size_t)img*CIN + ic)*HF + gy)*WF + gx];
    g_col[idx] = roundtf(v);
}

// ---------------------------------------------------------------------------
// TF32 tensor-core GEMM (NT): C[m][n] = act(sum_k A[m][k]*B[n][k] + bias[n])
// A, B already tf32-rounded fp32. BM=BN=128, BK=32, 256 threads (8 warps 2x4),
// warp tile 64x32, mma m16n8k8, cp.async double-buffered dynamic smem.
// flags: bit0 = relu, bit1 = round output to tf32.
// Requires M%128==0, N%128==0, K%32==0.
// ---------------------------------------------------------------------------
#define BK     32
#define SMROW  36                      // 32 data + 4 pad; banks (4r+c)%32 unique
#define SMBUF  (128*SMROW)             // floats per buffer
#define SMEM_GEMM_BYTES (4 * SMBUF * 4)  // 2 arrays x 2 buffers

__device__ __forceinline__ void cp16(uint32_t dst, const void* src)
{
    asm volatile("cp.async.ca.shared.global [%0], [%1], 16;" :: "r"(dst), "l"(src));
}

__global__ __launch_bounds__(256, 2)
void k_mma_tf32(const float* __restrict__ A, const float* __restrict__ B,
                const float* __restrict__ bias, float* __restrict__ C,
                int M, int N, int K, int flags)
{
    extern __shared__ float dynsmem[];
    float* Asm = dynsmem;              // [2][SMBUF]
    float* Bsm = dynsmem + 2*SMBUF;    // [2][SMBUF]

    const int tid  = threadIdx.x;
    const int warp = tid >> 5;
    const int lane = tid & 31;
    const int wm   = warp & 1;         // 0..1 -> 64-row slice
    const int wn   = warp >> 1;        // 0..3 -> 32-col slice
    const int m0 = blockIdx.y * 128;
    const int n0 = blockIdx.x * 128;

    // cp.async mapping: 2 threads per row, 64B (4 x 16B) each
    const int row  = tid >> 1;         // 0..127
    const int half = tid & 1;          // 0/1 -> col 0/16
    const float* Ap = A + (size_t)(m0 + row) * K + half*16;
    const float* Bp = B + (size_t)(n0 + row) * K + half*16;
    const uint32_t sA0 = (uint32_t)__cvta_generic_to_shared(Asm) + (row*SMROW + half*16)*4;
    const uint32_t sB0 = (uint32_t)__cvta_generic_to_shared(Bsm) + (row*SMROW + half*16)*4;
    const uint32_t bufb = SMBUF * 4;

    float acc[4][4][4];
#pragma unroll
    for (int mt = 0; mt < 4; mt++)
#pragma unroll
        for (int nt = 0; nt < 4; nt++)
#pragma unroll
            for (int r = 0; r < 4; r++) acc[mt][nt][r] = 0.f;

    const int abase = (wm*64 + (lane>>2)) * SMROW + (lane & 3);
    const int bbase = (wn*32 + (lane>>2)) * SMROW + (lane & 3);

    // prologue: slab 0 -> buffer 0
    {
#pragma unroll
        for (int i = 0; i < 4; i++) cp16(sA0 + i*16, Ap + i*4);
#pragma unroll
        for (int i = 0; i < 4; i++) cp16(sB0 + i*16, Bp + i*4);
        asm volatile("cp.async.commit_group;" ::: "memory");
    }

    const int nslab = K / BK;
    int buf = 0;
    for (int s = 0; s < nslab; s++) {
        if (s + 1 < nslab) {
            const int ko = (s + 1) * BK;
            const uint32_t bo = (uint32_t)(buf ^ 1) * bufb;
#pragma unroll
            for (int i = 0; i < 4; i++) cp16(sA0 + bo + i*16, Ap + ko + i*4);
#pragma unroll
            for (int i = 0; i < 4; i++) cp16(sB0 + bo + i*16, Bp + ko + i*4);
            asm volatile("cp.async.commit_group;" ::: "memory");
            asm volatile("cp.async.wait_group 1;" ::: "memory");
        } else {
            asm volatile("cp.async.wait_group 0;" ::: "memory");
        }
        __syncthreads();

        const uint32_t* as = (const uint32_t*)(Asm + buf*SMBUF);
        const uint32_t* bs = (const uint32_t*)(Bsm + buf*SMBUF);
#pragma unroll
        for (int ks = 0; ks < 4; ks++) {
            uint32_t af[4][4], bf[4][2];
#pragma unroll
            for (int mt = 0; mt < 4; mt++) {
                const int o = abase + mt*(16*SMROW) + ks*8;
                af[mt][0] = as[o];
                af[mt][1] = as[o + 8*SMROW];
                af[mt][2] = as[o + 4];
                af[mt][3] = as[o + 8*SMROW + 4];
            }
#pragma unroll
            for (int nt = 0; nt < 4; nt++) {
                const int o = bbase + nt*(8*SMROW) + ks*8;
                bf[nt][0] = bs[o];
                bf[nt][1] = bs[o + 4];
            }
#pragma unroll
            for (int mt = 0; mt < 4; mt++)
#pragma unroll
                for (int nt = 0; nt < 4; nt++) {
                    asm volatile(
                        "mma.sync.aligned.m16n8k8.row.col.f32.tf32.tf32.f32 "
                        "{%0,%1,%2,%3}, {%4,%5,%6,%7}, {%8,%9}, {%0,%1,%2,%3};\n"
                        : "+f"(acc[mt][nt][0]), "+f"(acc[mt][nt][1]),
                          "+f"(acc[mt][nt][2]), "+f"(acc[mt][nt][3])
                        : "r"(af[mt][0]), "r"(af[mt][1]),
                          "r"(af[mt][2]), "r"(af[mt][3]),
                          "r"(bf[nt][0]), "r"(bf[nt][1]));
                }
        }
        __syncthreads();
        buf ^= 1;
    }

    // epilogue
    const bool do_relu  = (flags & 1) != 0;
    const bool do_round = (flags & 2) != 0;
#pragma unroll
    for (int mt = 0; mt < 4; mt++) {
        const int rrow = m0 + wm*64 + mt*16 + (lane >> 2);
#pragma unroll
        for (int nt = 0; nt < 4; nt++) {
            const int col = n0 + wn*32 + nt*8 + 2*(lane & 3);
            const float bz0 = bias[col];
            const float bz1 = bias[col + 1];
            float v0 = acc[mt][nt][0] + bz0;
            float v1 = acc[mt][nt][1] + bz1;
            float v2 = acc[mt][nt][2] + bz0;
            float v3 = acc[mt][nt][3] + bz1;
            if (do_relu) {
                v0 = fmaxf(v0, 0.f); v1 = fmaxf(v1, 0.f);
                v2 = fmaxf(v2, 0.f); v3 = fmaxf(v3, 0.f);
            }
            if (do_round) {
                v0 = roundtf(v0); v1 = roundtf(v1);
                v2 = roundtf(v2); v3 = roundtf(v3);
            }
            *(float2*)(C + (size_t)rrow * N + col)       = make_float2(v0, v1);
            *(float2*)(C + (size_t)(rrow + 8) * N + col) = make_float2(v2, v3);
        }
    }
}

// ---------------------------------------------------------------------------
// Assemble: for each row r = ((img*4+s)*NQ + q) build
//   x[r][0..255] = tf32( coef(pix) * [cos(pi*qf), sin(pi*qf)] ),  area[r]
// ---------------------------------------------------------------------------
__global__ __launch_bounds__(256)
void k_assemble(const float* __restrict__ coord, const float* __restrict__ cell,
                const float* __restrict__ phase_w)
{
    const int r = blockIdx.x * 2 + (threadIdx.x >> 7);
    const int t = threadIdx.x & 127;

    const int img = r >> 18;          // / (4*NQ), NQ=2^16
    const int s   = (r >> 16) & 3;
    const int q   = r & (NQ - 1);

    const float cy = coord[2*q + 0];
    const float cx = coord[2*q + 1];

    const float vx = (s & 2) ? 1.f : -1.f;
    const float vy = (s & 1) ? 1.f : -1.f;
    const float RX  = 1.f / 128.f;
    const float EPS = 1e-6f;
    const float LO  = -1.0f + 1e-6f;
    const float HI  =  1.0f - 1e-6f;

    float cys = fminf(fmaxf(cy + (vx*RX + EPS), LO), HI);
    float cxs = fminf(fmaxf(cx + (vy*RX + EPS), LO), HI);

    int iy = (int)rintf(((cys + 1.f)*128.f - 1.f)*0.5f);
    int ix = (int)rintf(((cxs + 1.f)*128.f - 1.f)*0.5f);
    iy = min(max(iy, 0), 127);
    ix = min(max(ix, 0), 127);

    const float qcy = -1.f + (1.f/128.f) + (2.f/128.f)*(float)iy;
    const float qcx = -1.f + (1.f/128.f) + (2.f/128.f)*(float)ix;
    const float rel0 = (cy - qcy) * 128.f;
    const float rel1 = (cx - qcx) * 128.f;

    if (t == 0)
        g_area[r] = fabsf(rel0 * rel1) + 1e-9f;

    const float rc0 = cell[2*q + 0] * 128.f;
    const float rc1 = cell[2*q + 1] * 128.f;
    const float ph  = rc0 * phase_w[2*t + 0] + rc1 * phase_w[2*t + 1];

    const int pix = iy * WF + ix;
    const float* fp = g_freq + ((size_t)img * NPIX + pix) * HD;
    const float* cp = g_coef + ((size_t)img * NPIX + pix) * HD;

    const float qf = fp[2*t] * rel0 + fp[2*t + 1] * rel1 + ph;
    float sv, cv;
    __sincosf(3.14159265358979f * qf, &sv, &cv);

    const size_t base = (size_t)r * HD;
    g_x[base + t]       = roundtf(cp[t]       * cv);
    g_x[base + t + 128] = roundtf(cp[t + 128] * sv);
}

// ---------------------------------------------------------------------------
// Finalize: layer4 (256 -> 3), area-weighted blend (order [3,2,1,0]),
// bilinear-border of inp, write NCHW output. One warp per (img, q).
// ---------------------------------------------------------------------------
__global__ __launch_bounds__(256)
void k_finalize(const float* __restrict__ inp, const float* __restrict__ coord,
                const float* __restrict__ w4, const float* __restrict__ b4,
                float* __restrict__ out)
{
    __shared__ float sw4[3 * HD];
    for (int i = threadIdx.x; i < 3 * HD; i += 256) sw4[i] = w4[i];
    __syncthreads();

    const int warp = threadIdx.x >> 5;
    const int lane = threadIdx.x & 31;
    const int gq = blockIdx.x * 8 + warp;          // 0 .. 131071
    const int img = gq >> 16;
    const int q   = gq & (NQ - 1);

    float pred[4][3];
    float area[4];

#pragma unroll
    for (int s = 0; s < 4; s++) {
        const size_t rowi = ((size_t)(img*4 + s) << 16) + q;
        const float* h = g_h + rowi * HD;
        float a0 = 0.f, a1 = 0.f, a2 = 0.f;
#pragma unroll
        for (int j = 0; j < 8; j++) {
            const int idx = lane + 32*j;
            const float hv = h[idx];
            a0 += hv * sw4[idx];
            a1 += hv * sw4[HD + idx];
            a2 += hv * sw4[2*HD + idx];
        }
#pragma unroll
        for (int off = 16; off; off >>= 1) {
            a0 += __shfl_xor_sync(0xffffffffu, a0, off);
            a1 += __shfl_xor_sync(0xffffffffu, a1, off);
            a2 += __shfl_xor_sync(0xffffffffu, a2, off);
        }
        pred[s][0] = a0 + b4[0];
        pred[s][1] = a1 + b4[1];
        pred[s][2] = a2 + b4[2];
        area[s] = g_area[rowi];
    }

    const float tot = area[0] + area[1] + area[2] + area[3];
    const float w0 = area[3] / tot;   // order = [3,2,1,0]
    const float w1 = area[2] / tot;
    const float w2 = area[1] / tot;
    const float w3 = area[0] / tot;

    float ret[3];
#pragma unroll
    for (int c = 0; c < 3; c++)
        ret[c] = pred[0][c]*w0 + pred[1][c]*w1 + pred[2][c]*w2 + pred[3][c]*w3;

    // bilinear (border clamp) on inp at coord
    const float cy = coord[2*q + 0];
    const float cx = coord[2*q + 1];
    float y = fminf(fmaxf(((cy + 1.f)*128.f - 1.f)*0.5f, 0.f), 127.f);
    float x = fminf(fmaxf(((cx + 1.f)*128.f - 1.f)*0.5f, 0.f), 127.f);
    float y0f = floorf(y), x0f = floorf(x);
    int y0 = (int)y0f, x0 = (int)x0f;
    float wy = y - y0f, wx = x - x0f;
    int y1 = min(y0 + 1, 127), x1 = min(x0 + 1, 127);

    if (lane < 3) {
        const float* ip = inp + ((size_t)img*3 + lane) * NPIX;
        float v00 = ip[y0*WF + x0];
        float v01 = ip[y0*WF + x1];
        float v10 = ip[y1*WF + x0];
        float v11 = ip[y1*WF + x1];
        float bv = v00*(1.f-wy)*(1.f-wx) + v01*(1.f-wy)*wx
                 + v10*wy*(1.f-wx)       + v11*wy*wx;
        out[(((size_t)img*3 + lane) << 16) + q] = ret[lane] + bv;
    }
}

// ---------------------------------------------------------------------------
// Launch
// ---------------------------------------------------------------------------
extern "C" void kernel_launch(void* const* d_in, const int* in_sizes, int n_in,
                              void* d_out, int out_size)
{
    const float* feat    = (const float*)d_in[0];
    const float* inp     = (const float*)d_in[1];
    const float* coord   = (const float*)d_in[2];
    const float* cell    = (const float*)d_in[3];
    const float* coef_w  = (const float*)d_in[4];
    const float* coef_b  = (const float*)d_in[5];
    const float* freq_w  = (const float*)d_in[6];
    const float* freq_b  = (const float*)d_in[7];
    const float* phase_w = (const float*)d_in[8];
    const float* w1 = (const float*)d_in[9],  *b1 = (const float*)d_in[10];
    const float* w2 = (const float*)d_in[11], *b2 = (const float*)d_in[12];
    const float* w3 = (const float*)d_in[13], *b3 = (const float*)d_in[14];
    const float* w4 = (const float*)d_in[15], *b4 = (const float*)d_in[16];
    float* out = (float*)d_out;

    void *p_col, *p_coef, *p_freq, *p_x, *p_h, *p_wr;
    cudaGetSymbolAddress(&p_col,  g_col);
    cudaGetSymbolAddress(&p_coef, g_coef);
    cudaGetSymbolAddress(&p_freq, g_freq);
    cudaGetSymbolAddress(&p_x,    g_x);
    cudaGetSymbolAddress(&p_h,    g_h);
    cudaGetSymbolAddress(&p_wr,   g_wr);
    float* col_f  = (float*)p_col;
    float* coef_f = (float*)p_coef;
    float* freq_f = (float*)p_freq;
    float* x_f    = (float*)p_x;
    float* h_f    = (float*)p_h;
    float* wr_f   = (float*)p_wr;

    cudaFuncSetAttribute(k_mma_tf32,
                         cudaFuncAttributeMaxDynamicSharedMemorySize,
                         SMEM_GEMM_BYTES);

    // 0) pre-round weights to tf32
    k_round<<<(HD*HD + 255)/256, 256>>>(w1, wr_f + WR_W1, HD*HD);
    k_round<<<(HD*HD + 255)/256, 256>>>(w2, wr_f + WR_W2, HD*HD);
    k_round<<<(HD*HD + 255)/256, 256>>>(w3, wr_f + WR_W3, HD*HD);
    k_round<<<(HD*KCOL + 255)/256, 256>>>(coef_w, wr_f + WR_COEFW, HD*KCOL);
    k_round<<<(HD*KCOL + 255)/256, 256>>>(freq_w, wr_f + WR_FREQW, HD*KCOL);

    // 1) im2col (both images), tf32-rounded
    {
        const size_t total = (size_t)NIMG * NPIX * KCOL;
        k_im2col<<<(unsigned)((total + 255) / 256), 256>>>(feat);
    }

    // 2) conv-as-GEMM: coef & freq, NHWC fp32 output
    for (int img = 0; img < NIMG; img++) {
        const float* A = col_f + (size_t)img * NPIX * KCOL;
        k_mma_tf32<<<dim3(HD/128, NPIX/128), 256, SMEM_GEMM_BYTES>>>(
            A, wr_f + WR_COEFW, coef_b, coef_f + (size_t)img * NPIX * HD,
            NPIX, HD, KCOL, 0);
        k_mma_tf32<<<dim3(HD/128, NPIX/128), 256, SMEM_GEMM_BYTES>>>(
            A, wr_f + WR_FREQW, freq_b, freq_f + (size_t)img * NPIX * HD,
            NPIX, HD, KCOL, 0);
    }

    // 3) per-query assemble -> g_x rows (tf32-rounded)
    k_assemble<<<NROWS/2, 256>>>(coord, cell, phase_w);

    // 4) MLP layers 1..3 (flags: 1=relu, 2=round-out)
    k_mma_tf32<<<dim3(HD/128, NROWS/128), 256, SMEM_GEMM_BYTES>>>(
        x_f, wr_f + WR_W1, b1, h_f, NROWS, HD, HD, 3);
    k_mma_tf32<<<dim3(HD/128, NROWS/128), 256, SMEM_GEMM_BYTES>>>(
        h_f, wr_f + WR_W2, b2, x_f, NROWS, HD, HD, 3);
    k_mma_tf32<<<dim3(HD/128, NROWS/128), 256, SMEM_GEMM_BYTES>>>(
        x_f, wr_f + WR_W3, b3, h_f, NROWS, HD, HD, 1);

    // 5) layer4 + area blend + bilinear + write out
    k_finalize<<<(NIMG*NQ)/8, 256>>>(inp, coord, w4, b4, out);
}